// round 2
// baseline (speedup 1.0000x reference)
#include <cuda_runtime.h>

// DiffJPEG: per-8x8-block DCT -> quantize/dequantize -> IDCT.
// (32, 3, 512, 512) fp32. 8 threads per block (one image-row each),
// smem transposes between separable passes. High occupancy vs the
// register-resident one-thread-per-block design.

#define C1 0.4903926402f
#define C2 0.4619397663f
#define C3 0.4157348062f
#define C4 0.3535533906f
#define C5 0.2777851165f
#define C6 0.1913417162f
#define C7 0.0975451610f

__device__ __forceinline__ void dct8(float x[8]) {
    float s0 = x[0] + x[7], s1 = x[1] + x[6], s2 = x[2] + x[5], s3 = x[3] + x[4];
    float d0 = x[0] - x[7], d1 = x[1] - x[6], d2 = x[2] - x[5], d3 = x[3] - x[4];
    float e0 = s0 + s3, e1 = s1 + s2;
    float f0 = s0 - s3, f1 = s1 - s2;
    x[0] = C4 * (e0 + e1);
    x[4] = C4 * (e0 - e1);
    x[2] = C2 * f0 + C6 * f1;
    x[6] = C6 * f0 - C2 * f1;
    x[1] = C1 * d0 + C3 * d1 + C5 * d2 + C7 * d3;
    x[3] = C3 * d0 - C7 * d1 - C1 * d2 - C5 * d3;
    x[5] = C5 * d0 - C1 * d1 + C7 * d2 + C3 * d3;
    x[7] = C7 * d0 - C5 * d1 + C3 * d2 - C1 * d3;
}

__device__ __forceinline__ void idct8(float x[8]) {
    float a = C4 * (x[0] + x[4]);
    float b = C4 * (x[0] - x[4]);
    float e0 = a + C2 * x[2] + C6 * x[6];
    float e3 = a - C2 * x[2] - C6 * x[6];
    float e1 = b + C6 * x[2] - C2 * x[6];
    float e2 = b - C6 * x[2] + C2 * x[6];
    float o0 = C1 * x[1] + C3 * x[3] + C5 * x[5] + C7 * x[7];
    float o1 = C3 * x[1] - C7 * x[3] - C1 * x[5] - C5 * x[7];
    float o2 = C5 * x[1] - C1 * x[3] + C7 * x[5] + C3 * x[7];
    float o3 = C7 * x[1] - C5 * x[3] + C3 * x[5] - C1 * x[7];
    x[0] = e0 + o0;  x[7] = e0 - o0;
    x[1] = e1 + o1;  x[6] = e1 - o1;
    x[2] = e2 + o2;  x[5] = e2 - o2;
    x[3] = e3 + o3;  x[4] = e3 - o3;
}

static __device__ __constant__ float kQ[64] = {   // row-major Q[i][j]
    16.f, 11.f, 10.f, 16.f, 24.f,  40.f,  51.f,  61.f,
    12.f, 12.f, 14.f, 19.f, 26.f,  58.f,  60.f,  55.f,
    14.f, 13.f, 16.f, 24.f, 40.f,  57.f,  69.f,  56.f,
    14.f, 17.f, 22.f, 29.f, 51.f,  87.f,  80.f,  62.f,
    18.f, 22.f, 37.f, 56.f, 68.f, 109.f, 103.f,  77.f,
    24.f, 35.f, 55.f, 64.f, 81.f, 104.f, 113.f,  92.f,
    49.f, 64.f, 78.f, 87.f, 103.f,121.f, 120.f, 101.f,
    72.f, 92.f, 95.f, 98.f, 112.f,100.f, 103.f,  99.f
};

static constexpr int kW = 512;
static constexpr int kNumCtas = 32 * 3 * 64 * 2;   // 12288: each CTA = 32 blocks

__global__ __launch_bounds__(256, 6)
void diffjpeg_kernel(const float* __restrict__ in, float* __restrict__ out) {
    __shared__ float s[32][8][9];      // [block][row-of-transposed][col], padded
    __shared__ float qt[8][9];         // Q^T  : qt[r][j]  = Q[j][r]
    __shared__ float qti[8][9];        // 1/Q^T

    int t = threadIdx.x;
    if (t < 64) {
        int r = t >> 3, j = t & 7;
        float qv = kQ[j * 8 + r];
        qt[r][j]  = qv;
        qti[r][j] = 1.0f / qv;
    }

    int bk = t >> 3;        // block-in-CTA 0..31
    int r  = t & 7;         // row within 8x8 block

    unsigned cta = blockIdx.x;
    // 128 CTAs per (image,channel): 64 block-rows x 2 halves
    size_t base = ((size_t)(cta >> 7) << 18)
                + ((size_t)((cta & 127) >> 1) << 12)
                + ((size_t)(cta & 1) << 8);
    size_t off = base + (size_t)r * kW + bk * 8;

    float x[8];
    {
        float4 a = *reinterpret_cast<const float4*>(in + off);
        float4 b = *reinterpret_cast<const float4*>(in + off + 4);
        x[0] = a.x; x[1] = a.y; x[2] = a.z; x[3] = a.w;
        x[4] = b.x; x[5] = b.y; x[6] = b.z; x[7] = b.w;
    }

    // Pass 1: row DCT  -> X * D^T
    dct8(x);

    // Transpose 1 (conflict-free: banks (8bk + 9c + r) mod 32 injective)
#pragma unroll
    for (int c = 0; c < 8; c++) s[bk][c][r] = x[c];
    __syncthreads();
#pragma unroll
    for (int j = 0; j < 8; j++) x[j] = s[bk][r][j];

    // Pass 2: row DCT on transpose -> holds Y^T = (D X D^T)^T
    dct8(x);

    // Quantize/dequantize with transposed tables
#pragma unroll
    for (int j = 0; j < 8; j++)
        x[j] = rintf(x[j] * qti[r][j]) * qt[r][j];

    // Pass 3: row IDCT -> W^T * D
    idct8(x);

    // Transpose 2
    __syncthreads();
#pragma unroll
    for (int c = 0; c < 8; c++) s[bk][c][r] = x[c];
    __syncthreads();
#pragma unroll
    for (int j = 0; j < 8; j++) x[j] = s[bk][r][j];

    // Pass 4: row IDCT -> D^T W D, rows now match output layout
    idct8(x);

    {
        float4 a = make_float4(x[0], x[1], x[2], x[3]);
        float4 b = make_float4(x[4], x[5], x[6], x[7]);
        *reinterpret_cast<float4*>(out + off)     = a;
        *reinterpret_cast<float4*>(out + off + 4) = b;
    }
}

extern "C" void kernel_launch(void* const* d_in, const int* in_sizes, int n_in,
                              void* d_out, int out_size) {
    const float* img = (const float*)d_in[0];
    float* out = (float*)d_out;
    diffjpeg_kernel<<<kNumCtas, 256>>>(img, out);
}